// round 4
// baseline (speedup 1.0000x reference)
#include <cuda_runtime.h>
#include <math.h>

#define B 8
#define M 12
#define NN 32
#define D 256
#define C 1024      // N*N
#define CH 512      // C/R
#define BM 96

// Scratch (allocation-free rule: device globals)
__device__ float g_cov[BM * C];   // centered cov (sign -> mask)
__device__ float g_U[NN * CH];    // [n][o] collapsed-GEMM1 weights
__device__ float g_h[BM * CH];    // hidden after relu
__device__ float g_att[BM * C];   // final attention weights
__device__ int   g_uflag;         // U-ready counter (reset by k2k3)
__device__ int   g_cnt[B];        // att-ready counters (reset by kmix)

// ---- packed f32x2 helpers -------------------------------------------------
__device__ __forceinline__ unsigned long long ffma2(unsigned long long a,
                                                    unsigned long long b,
                                                    unsigned long long c) {
    unsigned long long d_;
    asm("fma.rn.f32x2 %0, %1, %2, %3;" : "=l"(d_) : "l"(a), "l"(b), "l"(c));
    return d_;
}
__device__ __forceinline__ unsigned long long pk2(float lo, float hi) {
    unsigned long long r;
    asm("mov.b64 %0, {%1, %2};" : "=l"(r) : "f"(lo), "f"(hi));
    return r;
}
__device__ __forceinline__ float unpk_add(unsigned long long v) {
    float lo, hi;
    asm("mov.b64 {%0, %1}, %2;" : "=f"(lo), "=f"(hi) : "l"(v));
    return lo + hi;
}

// ---------------------------------------------------------------------------
// kmix: grid 112.
//  blocks [96,112): U[n][o] = rowsum_n + 2*colsum_n - diag_n of W1 row o.
//  blocks [0,96):   per bm: S, cov sign (register-blocked f32x2), then spin
//                   on U and compute h = relu(U^T S / 512).
// Dyn smem: xs (natural, 8192 f) | xst/red/smT (8448 f) | sp (256) | S (32).
// ---------------------------------------------------------------------------
__global__ void __launch_bounds__(256) kmix(const float* __restrict__ x,
                                            const float* __restrict__ W1) {
    extern __shared__ float sm[];
    const int tid = threadIdx.x;
    const int w = tid >> 5, lane = tid & 31;

    if (blockIdx.x == 0 && tid < B) g_cnt[tid] = 0;  // reset for k2k3

    if (blockIdx.x >= BM) {
        // ---- U blocks: 16 blocks x 8 warps x 4 o = 512 outputs ----
        const int ub = blockIdx.x - BM;
        float* smT = sm + 8192 + w * 1056;  // 33x32 per-warp pad region
        #pragma unroll
        for (int i = 0; i < 4; i++) {
            const int o = ub * 32 + w * 4 + i;
            const float* row = W1 + (size_t)o * C;
            float r[32], cs = 0.f;
            #pragma unroll
            for (int j = 0; j < 32; j++) { r[j] = row[j * 32 + lane]; cs += r[j]; }
            #pragma unroll
            for (int j = 0; j < 32; j++) smT[j * 33 + lane] = r[j];
            __syncwarp();
            float rs = 0.f;
            #pragma unroll
            for (int mm = 0; mm < 32; mm++) rs += smT[lane * 33 + mm];
            const float dg = smT[lane * 33 + lane];
            g_U[lane * CH + o] = rs + 2.f * cs - dg;
            __syncwarp();
        }
        __threadfence();
        __syncthreads();
        if (tid == 0) atomicAdd(&g_uflag, 1);
        return;
    }

    // ---- bm blocks ----
    const int bm = blockIdx.x;
    float* xs  = sm;            // natural [n*256+d]
    float* xst = sm + 8192;     // transposed [d*33+n]; reused as red buffer
    float* sp  = sm + 16640;
    float* S   = sm + 16896;

    const float4* xg4 = (const float4*)(x + (size_t)bm * (NN * D));
    for (int i = tid; i < 2048; i += 256) {
        const float4 v = xg4[i];
        ((float4*)xs)[i] = v;
        const int n = i >> 6, d = (i & 63) * 4;
        xst[(d + 0) * 33 + n] = v.x; xst[(d + 1) * 33 + n] = v.y;
        xst[(d + 2) * 33 + n] = v.z; xst[(d + 3) * 33 + n] = v.w;
    }
    __syncthreads();

    // register fill: xk = x[k=lane][32w .. 32w+31], packed in pairs
    unsigned long long xk2[16];
    float spv = 0.f;
    const int d0 = w * 32;
    #pragma unroll
    for (int j = 0; j < 16; j++) {
        const float lo = xst[(d0 + 2 * j) * 33 + lane];
        const float hi = xst[(d0 + 2 * j + 1) * 33 + lane];
        xk2[j] = pk2(lo, hi);
        spv += lo + hi;
    }
    sp[w * 32 + lane] = spv;
    __syncthreads();                 // also protects xst reuse below
    if (tid < 32) {
        float s = 0.f;
        #pragma unroll
        for (int ww = 0; ww < 8; ww++) s += sp[ww * 32 + tid];
        S[tid] = s;
    }
    __syncthreads();

    // cov partials: acc2[n] += x[n][d-pair] * xk[d-pair]
    unsigned long long acc2[32];
    #pragma unroll
    for (int n = 0; n < NN; n++) acc2[n] = 0ull;

    const ulonglong2* xs2 = (const ulonglong2*)xs;   // 64 u2 per row
    #pragma unroll
    for (int n = 0; n < NN; n++) {
        const ulonglong2* rowp = xs2 + n * 64 + w * 8;
        #pragma unroll
        for (int jj = 0; jj < 8; jj++) {
            const ulonglong2 bv = rowp[jj];          // broadcast LDS.128
            acc2[n] = ffma2(bv.x, xk2[2 * jj], acc2[n]);
            acc2[n] = ffma2(bv.y, xk2[2 * jj + 1], acc2[n]);
        }
    }

    float* red = xst;   // 8x1024 partials
    #pragma unroll
    for (int n = 0; n < NN; n++) red[w * 1024 + n * 32 + lane] = unpk_add(acc2[n]);
    __syncthreads();

    {   // combine 8 warp-partials, subtract S_n S_k / 256, store sign source
        const float4* red4 = (const float4*)red;
        float4 cv = make_float4(0.f, 0.f, 0.f, 0.f);
        #pragma unroll
        for (int ww = 0; ww < 8; ww++) {
            const float4 t = red4[ww * 256 + tid];
            cv.x += t.x; cv.y += t.y; cv.z += t.z; cv.w += t.w;
        }
        const int n = tid >> 3, k0 = (tid & 7) * 4;
        const float sn = S[n] * (1.f / 256.f);
        cv.x -= sn * S[k0 + 0]; cv.y -= sn * S[k0 + 1];
        cv.z -= sn * S[k0 + 2]; cv.w -= sn * S[k0 + 3];
        ((float4*)(g_cov + (size_t)bm * C))[tid] = cv;
    }

    // h = relu( sum_n U[n][o] * S[n] / 512 )
    if (tid == 0) { while (atomicAdd(&g_uflag, 0) < 16) { } }
    __syncthreads();
    __threadfence();
    #pragma unroll
    for (int t = 0; t < 2; t++) {
        const int o = tid + t * 256;
        float acc = 0.f;
        #pragma unroll
        for (int n = 0; n < NN; n++) acc += g_U[n * CH + o] * S[n];
        g_h[(size_t)bm * CH + o] = fmaxf(acc * (1.f / 512.f), 0.f);
    }
}

// ---------------------------------------------------------------------------
// k2k3 fused: grid 224, 384 threads.
//  blocks [0,128):  k2 — e2 tile of 64 c (= att rows 2ct,2ct+1) per (ct,b),
//                   fused sigmoid+mask+softmax, release g_cnt[b].
//  blocks [128,224): k3 — per bm, spin on g_cnt[b]==16, AV with f32x2.
// ---------------------------------------------------------------------------
__global__ void __launch_bounds__(384) k2k3(const float* __restrict__ W2,
                                            const float* __restrict__ x,
                                            float* __restrict__ out) {
    __shared__ float sm3[8192 + 1024];   // xs | att (k3 only)
    const int tid = threadIdx.x;
    const int wlane = tid & 31;

    if (blockIdx.x == 0 && tid == 0) atomicExch(&g_uflag, 0);  // reset for kmix

    if (blockIdx.x < 128) {
        // ---- k2 ----
        const int ct = blockIdx.x >> 3, b = blockIdx.x & 7;
        const int m = tid / 32;
        const int bm = b * M + m;

        unsigned long long hh[8];
        const ulonglong2* hu = (const ulonglong2*)(g_h + (size_t)bm * CH);
        #pragma unroll
        for (int jj = 0; jj < 4; jj++) {
            const ulonglong2 t = hu[jj * 32 + wlane];
            hh[2 * jj] = t.x; hh[2 * jj + 1] = t.y;
        }

        float res0 = 0.f, res1 = 0.f;
        #pragma unroll 2
        for (int cl = 0; cl < 64; cl++) {
            const int c = ct * 64 + cl;
            const ulonglong2* w2r = (const ulonglong2*)(W2 + (size_t)c * CH);
            unsigned long long a2 = 0ull;
            #pragma unroll
            for (int jj = 0; jj < 4; jj++) {
                const ulonglong2 bv = w2r[jj * 32 + wlane];
                a2 = ffma2(bv.x, hh[2 * jj], a2);
                a2 = ffma2(bv.y, hh[2 * jj + 1], a2);
            }
            float v = unpk_add(a2);
            #pragma unroll
            for (int off = 16; off; off >>= 1) v += __shfl_xor_sync(0xffffffffu, v, off);
            if (cl < 32) { if (cl == wlane) res0 = v; }
            else         { if (cl - 32 == wlane) res1 = v; }
        }

        const int n0 = ct * 2, n1 = ct * 2 + 1;
        const float cv0 = g_cov[(size_t)bm * C + n0 * NN + wlane];
        const float cv1 = g_cov[(size_t)bm * C + n1 * NN + wlane];
        const float sg0 = 1.f / (1.f + __expf(-res0));
        const float sg1 = 1.f / (1.f + __expf(-res1));
        float ev0 = (cv0 > 0.f) ? __expf(sg0) : 0.f;
        float ev1 = (cv1 > 0.f) ? __expf(sg1) : 0.f;
        float s0 = ev0, s1 = ev1;
        #pragma unroll
        for (int off = 16; off; off >>= 1) {
            s0 += __shfl_xor_sync(0xffffffffu, s0, off);
            s1 += __shfl_xor_sync(0xffffffffu, s1, off);
        }
        g_att[(size_t)bm * C + n0 * NN + wlane] = ev0 / s0;
        g_att[(size_t)bm * C + n1 * NN + wlane] = ev1 / s1;

        __threadfence();
        __syncthreads();
        if (tid == 0) atomicAdd(&g_cnt[b], 1);
        return;
    }

    // ---- k3 ----
    const int bm = blockIdx.x - 128;
    const int b = bm / M;
    float* xs  = sm3;
    float* att = sm3 + 8192;

    const float4* xg4 = (const float4*)(x + (size_t)bm * (NN * D));
    for (int i = tid; i < 2048; i += 384) ((float4*)xs)[i] = xg4[i];

    if (tid == 0) { while (atomicAdd(&g_cnt[b], 0) < 16) { } }
    __syncthreads();
    __threadfence();

    if (tid < 256) ((float4*)att)[tid] = ((const float4*)(g_att + (size_t)bm * C))[tid];
    __syncthreads();

    if (tid < 256) {
        unsigned long long xv2[16];
        #pragma unroll
        for (int kk = 0; kk < 16; kk++)
            xv2[kk] = pk2(xs[(2 * kk) * D + tid], xs[(2 * kk + 1) * D + tid]);

        float* ot = out + (size_t)bm * (NN * D);
        #pragma unroll 4
        for (int n = 0; n < NN; n++) {
            const ulonglong2* ar = (const ulonglong2*)(att + n * NN);
            unsigned long long a2 = 0ull;
            #pragma unroll
            for (int jj = 0; jj < 8; jj++) {
                const ulonglong2 bv = ar[jj];        // broadcast LDS.128
                a2 = ffma2(bv.x, xv2[2 * jj], a2);
                a2 = ffma2(bv.y, xv2[2 * jj + 1], a2);
            }
            ot[n * D + tid] = unpk_add(a2);
        }
    }
}

// ---------------------------------------------------------------------------
extern "C" void kernel_launch(void* const* d_in, const int* in_sizes, int n_in,
                              void* d_out, int out_size) {
    const float* x  = (const float*)d_in[0];
    const float* W1 = (const float*)d_in[1];
    const float* W2 = (const float*)d_in[2];
    float* out = (float*)d_out;

    const int smem = (8192 + 8448 + 256 + 32) * sizeof(float);  // 67712 B
    cudaFuncSetAttribute(kmix, cudaFuncAttributeMaxDynamicSharedMemorySize, smem);

    kmix<<<BM + 16, 256, smem>>>(x, W1);
    k2k3<<<128 + BM, 384>>>(W2, x, out);
}

// round 5
// speedup vs baseline: 1.0576x; 1.0576x over previous
#include <cuda_runtime.h>
#include <math.h>

#define B 8
#define M 12
#define NN 32
#define D 256
#define C 1024      // N*N
#define CH 512      // C/R
#define BM 96

// Scratch (allocation-free rule: device globals)
__device__ float g_cov[BM * C];   // centered cov (sign -> mask)
__device__ float g_U[NN * CH];    // [n][o] collapsed-GEMM1 weights
__device__ float g_h[BM * CH];    // hidden after relu
__device__ float g_att[BM * C];   // final attention weights
__device__ int   g_uflag;         // U-ready counter (reset by k3 each run)

// ---- packed f32x2 helpers -------------------------------------------------
__device__ __forceinline__ unsigned long long ffma2(unsigned long long a,
                                                    unsigned long long b,
                                                    unsigned long long c) {
    unsigned long long d_;
    asm("fma.rn.f32x2 %0, %1, %2, %3;" : "=l"(d_) : "l"(a), "l"(b), "l"(c));
    return d_;
}
__device__ __forceinline__ unsigned long long pk2(float lo, float hi) {
    unsigned long long r;
    asm("mov.b64 %0, {%1, %2};" : "=l"(r) : "f"(lo), "f"(hi));
    return r;
}
__device__ __forceinline__ float unpk_add(unsigned long long v) {
    float lo, hi;
    asm("mov.b64 {%0, %1}, %2;" : "=f"(lo), "=f"(hi) : "l"(v));
    return lo + hi;
}

// ---------------------------------------------------------------------------
// kmix: grid 112.
//  blocks [96,112): U[n][o] = rowsum_n + 2*colsum_n - diag_n of W1 row o.
//  blocks [0,96):   per bm: S, cov sign (register-blocked f32x2), then spin
//                   on U and compute h = relu(U^T S / 512).
// ---------------------------------------------------------------------------
__global__ void __launch_bounds__(256) kmix(const float* __restrict__ x,
                                            const float* __restrict__ W1) {
    extern __shared__ float sm[];
    const int tid = threadIdx.x;
    const int w = tid >> 5, lane = tid & 31;

    if (blockIdx.x >= BM) {
        // ---- U blocks: 16 blocks x 8 warps x 4 o = 512 outputs ----
        const int ub = blockIdx.x - BM;
        float* smT = sm + 8192 + w * 1056;  // 33x32 per-warp pad region
        #pragma unroll
        for (int i = 0; i < 4; i++) {
            const int o = ub * 32 + w * 4 + i;
            const float* row = W1 + (size_t)o * C;
            float r[32], cs = 0.f;
            #pragma unroll
            for (int j = 0; j < 32; j++) { r[j] = row[j * 32 + lane]; cs += r[j]; }
            #pragma unroll
            for (int j = 0; j < 32; j++) smT[j * 33 + lane] = r[j];
            __syncwarp();
            float rs = 0.f;
            #pragma unroll
            for (int mm = 0; mm < 32; mm++) rs += smT[lane * 33 + mm];
            const float dg = smT[lane * 33 + lane];
            g_U[lane * CH + o] = rs + 2.f * cs - dg;
            __syncwarp();
        }
        __threadfence();
        __syncthreads();
        if (tid == 0) atomicAdd(&g_uflag, 1);
        return;
    }

    // ---- bm blocks ----
    const int bm = blockIdx.x;
    float* xs  = sm;            // natural [n*256+d]
    float* xst = sm + 8192;     // transposed [d*33+n]; reused as red buffer
    float* sp  = sm + 16640;
    float* S   = sm + 16896;

    const float4* xg4 = (const float4*)(x + (size_t)bm * (NN * D));
    for (int i = tid; i < 2048; i += 256) {
        const float4 v = xg4[i];
        ((float4*)xs)[i] = v;
        const int n = i >> 6, d = (i & 63) * 4;
        xst[(d + 0) * 33 + n] = v.x; xst[(d + 1) * 33 + n] = v.y;
        xst[(d + 2) * 33 + n] = v.z; xst[(d + 3) * 33 + n] = v.w;
    }
    __syncthreads();

    // register fill: xk = x[k=lane][32w .. 32w+31], packed in pairs
    unsigned long long xk2[16];
    float spv = 0.f;
    const int d0 = w * 32;
    #pragma unroll
    for (int j = 0; j < 16; j++) {
        const float lo = xst[(d0 + 2 * j) * 33 + lane];
        const float hi = xst[(d0 + 2 * j + 1) * 33 + lane];
        xk2[j] = pk2(lo, hi);
        spv += lo + hi;
    }
    sp[w * 32 + lane] = spv;
    __syncthreads();                 // also protects xst reuse below
    if (tid < 32) {
        float s = 0.f;
        #pragma unroll
        for (int ww = 0; ww < 8; ww++) s += sp[ww * 32 + tid];
        S[tid] = s;
    }
    __syncthreads();

    // cov partials: acc2[n] += x[n][d-pair] * xk[d-pair]
    unsigned long long acc2[32];
    #pragma unroll
    for (int n = 0; n < NN; n++) acc2[n] = 0ull;

    const ulonglong2* xs2 = (const ulonglong2*)xs;   // 64 u2 per row
    #pragma unroll
    for (int n = 0; n < NN; n++) {
        const ulonglong2* rowp = xs2 + n * 64 + w * 8;
        #pragma unroll
        for (int jj = 0; jj < 8; jj++) {
            const ulonglong2 bv = rowp[jj];          // broadcast LDS.128
            acc2[n] = ffma2(bv.x, xk2[2 * jj], acc2[n]);
            acc2[n] = ffma2(bv.y, xk2[2 * jj + 1], acc2[n]);
        }
    }

    float* red = xst;   // 8x1024 partials
    #pragma unroll
    for (int n = 0; n < NN; n++) red[w * 1024 + n * 32 + lane] = unpk_add(acc2[n]);
    __syncthreads();

    {   // combine 8 warp-partials, subtract S_n S_k / 256, store sign source
        const float4* red4 = (const float4*)red;
        float4 cv = make_float4(0.f, 0.f, 0.f, 0.f);
        #pragma unroll
        for (int ww = 0; ww < 8; ww++) {
            const float4 t = red4[ww * 256 + tid];
            cv.x += t.x; cv.y += t.y; cv.z += t.z; cv.w += t.w;
        }
        const int n = tid >> 3, k0 = (tid & 7) * 4;
        const float sn = S[n] * (1.f / 256.f);
        cv.x -= sn * S[k0 + 0]; cv.y -= sn * S[k0 + 1];
        cv.z -= sn * S[k0 + 2]; cv.w -= sn * S[k0 + 3];
        ((float4*)(g_cov + (size_t)bm * C))[tid] = cv;
    }

    // h = relu( sum_n U[n][o] * S[n] / 512 )
    if (tid == 0) { while (atomicAdd(&g_uflag, 0) < 16) { } }
    __syncthreads();
    __threadfence();
    #pragma unroll
    for (int t = 0; t < 2; t++) {
        const int o = tid + t * 256;
        float acc = 0.f;
        #pragma unroll
        for (int n = 0; n < NN; n++) acc += g_U[n * CH + o] * S[n];
        g_h[(size_t)bm * CH + o] = fmaxf(acc * (1.f / 512.f), 0.f);
    }
}

// ---------------------------------------------------------------------------
// k2: grid (16 ct, 8 b), 384 thr (warp = m). e2 for c-tile of 64 (= att rows
// 2ct, 2ct+1): 4 dots per iteration with interleaved butterfly reductions
// (4 independent SHFL chains in flight), then fused sigmoid + mask + warp
// softmax (no max pass: diag always unmasked, values in (0,1)). Writes att.
// ---------------------------------------------------------------------------
__global__ void __launch_bounds__(384) k2_gemm_softmax(const float* __restrict__ W2) {
    const int ct = blockIdx.x, b = blockIdx.y;
    const int tid = threadIdx.x;
    const int m = tid >> 5, lane = tid & 31;
    const int bm = b * M + m;

    unsigned long long hh[8];
    const ulonglong2* hu = (const ulonglong2*)(g_h + (size_t)bm * CH);
    #pragma unroll
    for (int jj = 0; jj < 4; jj++) {
        const ulonglong2 t = hu[jj * 32 + lane];
        hh[2 * jj] = t.x; hh[2 * jj + 1] = t.y;
    }

    float res0 = 0.f, res1 = 0.f;
    #pragma unroll
    for (int cb = 0; cb < 64; cb += 4) {
        float v[4];
        #pragma unroll
        for (int q = 0; q < 4; q++) {
            const int c = ct * 64 + cb + q;
            const ulonglong2* w2r = (const ulonglong2*)(W2 + (size_t)c * CH);
            unsigned long long a2 = 0ull;
            #pragma unroll
            for (int jj = 0; jj < 4; jj++) {
                const ulonglong2 bv = w2r[jj * 32 + lane];
                a2 = ffma2(bv.x, hh[2 * jj], a2);
                a2 = ffma2(bv.y, hh[2 * jj + 1], a2);
            }
            v[q] = unpk_add(a2);
        }
        #pragma unroll
        for (int off = 16; off; off >>= 1) {   // 4 chains interleaved
            #pragma unroll
            for (int q = 0; q < 4; q++)
                v[q] += __shfl_xor_sync(0xffffffffu, v[q], off);
        }
        #pragma unroll
        for (int q = 0; q < 4; q++) {
            const int cl = cb + q;
            if (cl < 32) { if (cl == lane) res0 = v[q]; }
            else         { if (cl - 32 == lane) res1 = v[q]; }
        }
    }

    // rows n0 = 2ct (res0), n1 = 2ct+1 (res1); k = lane
    const int n0 = ct * 2, n1 = ct * 2 + 1;
    const float cv0 = g_cov[(size_t)bm * C + n0 * NN + lane];
    const float cv1 = g_cov[(size_t)bm * C + n1 * NN + lane];
    const float sg0 = 1.f / (1.f + __expf(-res0));
    const float sg1 = 1.f / (1.f + __expf(-res1));
    float ev0 = (cv0 > 0.f) ? __expf(sg0) : 0.f;
    float ev1 = (cv1 > 0.f) ? __expf(sg1) : 0.f;
    float s0 = ev0, s1 = ev1;
    #pragma unroll
    for (int off = 16; off; off >>= 1) {
        s0 += __shfl_xor_sync(0xffffffffu, s0, off);
        s1 += __shfl_xor_sync(0xffffffffu, s1, off);
    }
    g_att[(size_t)bm * C + n0 * NN + lane] = ev0 / s0;
    g_att[(size_t)bm * C + n1 * NN + lane] = ev1 / s1;
}

// ---------------------------------------------------------------------------
// k3: per bm, 256 thr. Pure AV: out[n][d=tid] = sum_k att[n][k] * x[k][d].
// x column cached in 16 f32x2 regs; att rows via LDS.128 broadcast.
// Also resets g_uflag for the next graph replay.
// ---------------------------------------------------------------------------
__global__ void __launch_bounds__(256) k3_av(const float* __restrict__ x,
                                             float* __restrict__ out) {
    const int bm = blockIdx.x;
    __shared__ float xs[NN * D];   // 32 KB
    __shared__ float att[C];       // 4 KB

    if (blockIdx.x == 0 && threadIdx.x == 0) atomicExch(&g_uflag, 0);

    const int tid = threadIdx.x;
    const float4* xg4 = (const float4*)(x + (size_t)bm * (NN * D));
    float4* xs4 = (float4*)xs;
    #pragma unroll
    for (int i = 0; i < 8; i++) xs4[tid + i * 256] = xg4[tid + i * 256];

    ((float4*)att)[tid] = ((const float4*)(g_att + (size_t)bm * C))[tid];
    __syncthreads();

    unsigned long long xv2[16];
    #pragma unroll
    for (int kk = 0; kk < 16; kk++)
        xv2[kk] = pk2(xs[(2 * kk) * D + tid], xs[(2 * kk + 1) * D + tid]);

    float* ot = out + (size_t)bm * (NN * D);
    #pragma unroll 4
    for (int n = 0; n < NN; n++) {
        const ulonglong2* ar = (const ulonglong2*)(att + n * NN);
        unsigned long long a2 = 0ull;
        #pragma unroll
        for (int jj = 0; jj < 8; jj++) {
            const ulonglong2 bv = ar[jj];        // broadcast LDS.128
            a2 = ffma2(bv.x, xv2[2 * jj], a2);
            a2 = ffma2(bv.y, xv2[2 * jj + 1], a2);
        }
        ot[n * D + tid] = unpk_add(a2);
    }
}

// ---------------------------------------------------------------------------
extern "C" void kernel_launch(void* const* d_in, const int* in_sizes, int n_in,
                              void* d_out, int out_size) {
    const float* x  = (const float*)d_in[0];
    const float* W1 = (const float*)d_in[1];
    const float* W2 = (const float*)d_in[2];
    float* out = (float*)d_out;

    const int smem = (8192 + 8448 + 256 + 32) * sizeof(float);  // 67712 B
    cudaFuncSetAttribute(kmix, cudaFuncAttributeMaxDynamicSharedMemorySize, smem);

    kmix<<<BM + 16, 256, smem>>>(x, W1);
    k2_gemm_softmax<<<dim3(16, B), 384>>>(W2);
    k3_av<<<BM, 256>>>(x, out);
}

// round 6
// speedup vs baseline: 1.3901x; 1.3144x over previous
#include <cuda_runtime.h>
#include <math.h>

#define B 8
#define M 12
#define NN 32
#define D 256
#define C 1024      // N*N
#define CH 512      // C/R
#define BM 96

typedef unsigned long long ull;

// Scratch (allocation-free rule: device globals)
__device__ float g_S[BM * NN];    // row sums per bm
__device__ float g_cov[BM * C];   // centered cov (sign -> mask)
__device__ float g_h[BM * CH];    // hidden after relu
__device__ float g_att[BM * C];   // final attention weights
__device__ int   g_scnt;          // S-ready counter (reset by k3 each run)

// ---- packed f32x2 helpers -------------------------------------------------
__device__ __forceinline__ ull ffma2(ull a, ull b, ull c) {
    ull d_;
    asm("fma.rn.f32x2 %0, %1, %2, %3;" : "=l"(d_) : "l"(a), "l"(b), "l"(c));
    return d_;
}
__device__ __forceinline__ ull pk2(float lo, float hi) {
    ull r;
    asm("mov.b64 %0, {%1, %2};" : "=l"(r) : "f"(lo), "f"(hi));
    return r;
}
__device__ __forceinline__ float unpk_add(ull v) {
    float lo, hi;
    asm("mov.b64 {%0, %1}, %2;" : "=f"(lo), "=f"(hi) : "l"(v));
    return lo + hi;
}

// smem swizzle for k2 tiles: q in [0,128) float4 units, chunk = q>>4
#define SWZ(q) (((q) & 0x70) | (((q) ^ ((q) >> 4)) & 0x0F))

// ---------------------------------------------------------------------------
// kA: grid 112, 256 thr.
//  blocks [0,96):   per bm: S (published EARLY + counter), cov sign. No wait.
//  blocks [96,112): U[n][o] = rowsum+2*colsum-diag of W1 row o (smem only),
//                   then spin on S counter and compute h = relu(U^T S / 512).
// ---------------------------------------------------------------------------
__global__ void __launch_bounds__(256) kA(const float* __restrict__ x,
                                          const float* __restrict__ W1) {
    extern __shared__ float sm[];
    const int tid = threadIdx.x;
    const int w = tid >> 5, lane = tid & 31;

    if (blockIdx.x >= BM) {
        // ---- U + h blocks: block ub owns o-range [ub*32, ub*32+32) ----
        const int ub = blockIdx.x - BM;
        float* smT  = sm + w * 1056;     // per-warp 33x32 transpose buf
        float* U_t  = sm + 8448;         // [n*33 + o_local], 1056
        float* S_sm = sm + 9504;         // 96x32 = 3072

        #pragma unroll
        for (int i = 0; i < 4; i++) {
            const int ol = w * 4 + i;
            const int o  = ub * 32 + ol;
            const float* row = W1 + (size_t)o * C;
            float r[32], cs = 0.f;
            #pragma unroll
            for (int j = 0; j < 32; j++) { r[j] = row[j * 32 + lane]; cs += r[j]; }
            #pragma unroll
            for (int j = 0; j < 32; j++) smT[j * 33 + lane] = r[j];
            __syncwarp();
            float rs = 0.f;
            #pragma unroll
            for (int mm = 0; mm < 32; mm++) rs += smT[lane * 33 + mm];
            const float dg = smT[lane * 33 + lane];
            U_t[lane * 33 + ol] = rs + 2.f * cs - dg;   // lane = n
            __syncwarp();
        }
        __syncthreads();

        if (tid == 0) { while (atomicAdd(&g_scnt, 0) < BM) { } }
        __syncthreads();
        __threadfence();

        for (int i = tid; i < BM * NN; i += 256) S_sm[i] = g_S[i];
        __syncthreads();

        const int ol = lane;             // o local
        float u[32];
        #pragma unroll
        for (int n = 0; n < NN; n++) u[n] = U_t[n * 33 + ol];

        #pragma unroll
        for (int bmi = 0; bmi < 12; bmi++) {
            const int bm = w * 12 + bmi;
            float acc = 0.f;
            #pragma unroll
            for (int n = 0; n < NN; n++) acc += u[n] * S_sm[bm * 32 + n];
            g_h[(size_t)bm * CH + ub * 32 + ol] = fmaxf(acc * (1.f / 512.f), 0.f);
        }
        return;
    }

    // ---- bm blocks ----
    const int bm = blockIdx.x;
    float* xs  = sm;            // natural [n*256+d]
    float* xst = sm + 8192;     // transposed [d*33+n]; reused as red buffer
    float* sp  = sm + 16640;
    float* S   = sm + 16896;

    const float4* xg4 = (const float4*)(x + (size_t)bm * (NN * D));
    for (int i = tid; i < 2048; i += 256) {
        const float4 v = xg4[i];
        ((float4*)xs)[i] = v;
        const int n = i >> 6, d = (i & 63) * 4;
        xst[(d + 0) * 33 + n] = v.x; xst[(d + 1) * 33 + n] = v.y;
        xst[(d + 2) * 33 + n] = v.z; xst[(d + 3) * 33 + n] = v.w;
    }
    __syncthreads();

    // register fill: xk = x[k=lane][32w .. 32w+31], packed in pairs
    ull xk2[16];
    float spv = 0.f;
    const int d0 = w * 32;
    #pragma unroll
    for (int j = 0; j < 16; j++) {
        const float lo = xst[(d0 + 2 * j) * 33 + lane];
        const float hi = xst[(d0 + 2 * j + 1) * 33 + lane];
        xk2[j] = pk2(lo, hi);
        spv += lo + hi;
    }
    sp[w * 32 + lane] = spv;
    __syncthreads();
    if (tid < 32) {
        float s = 0.f;
        #pragma unroll
        for (int ww = 0; ww < 8; ww++) s += sp[ww * 32 + tid];
        S[tid] = s;
        g_S[bm * 32 + tid] = s;      // publish S early
        __threadfence();
    }
    __syncthreads();
    if (tid == 0) atomicAdd(&g_scnt, 1);

    // cov partials: acc2[n] += x[n][d-pair] * xk[d-pair]
    ull acc2[32];
    #pragma unroll
    for (int n = 0; n < NN; n++) acc2[n] = 0ull;

    const ulonglong2* xs2 = (const ulonglong2*)xs;   // 64 u2 per row
    #pragma unroll
    for (int n = 0; n < NN; n++) {
        const ulonglong2* rowp = xs2 + n * 64 + w * 8;
        #pragma unroll
        for (int jj = 0; jj < 8; jj++) {
            const ulonglong2 bv = rowp[jj];          // broadcast LDS.128
            acc2[n] = ffma2(bv.x, xk2[2 * jj], acc2[n]);
            acc2[n] = ffma2(bv.y, xk2[2 * jj + 1], acc2[n]);
        }
    }

    float* red = xst;   // 8x1024 partials
    #pragma unroll
    for (int n = 0; n < NN; n++) red[w * 1024 + n * 32 + lane] = unpk_add(acc2[n]);
    __syncthreads();

    {   // combine 8 warp-partials, subtract S_n S_k / 256
        const float4* red4 = (const float4*)red;
        float4 cv = make_float4(0.f, 0.f, 0.f, 0.f);
        #pragma unroll
        for (int ww = 0; ww < 8; ww++) {
            const float4 t = red4[ww * 256 + tid];
            cv.x += t.x; cv.y += t.y; cv.z += t.z; cv.w += t.w;
        }
        const int n = tid >> 3, k0 = (tid & 7) * 4;
        const float sn = S[n] * (1.f / 256.f);
        cv.x -= sn * S[k0 + 0]; cv.y -= sn * S[k0 + 1];
        cv.z -= sn * S[k0 + 2]; cv.w -= sn * S[k0 + 3];
        ((float4*)(g_cov + (size_t)bm * C))[tid] = cv;
    }
}

// ---------------------------------------------------------------------------
// k2: grid (16 ct, 8 b), 256 thr. W2 tile (64x512, 128KB) + h (12x512, 24KB)
// staged in swizzled smem. Thread (c2 = tid>>3, kc = tid&7) owns rows
// {2c2, 2c2+1} x all 12 m over k-chunk [kc*64, kc*64+64): each W2 value loaded
// once serves 12 m (12x less L1 traffic). Partials combined in smem, then
// fused sigmoid + mask + warp softmax; writes final att rows 2ct, 2ct+1.
// ---------------------------------------------------------------------------
__global__ void __launch_bounds__(256) k2_gemm_softmax(const float* __restrict__ W2) {
    extern __shared__ float s2[];
    const int ct = blockIdx.x, b = blockIdx.y;
    const int tid = threadIdx.x;
    const int w = tid >> 5, lane = tid & 31;

    // stage W2 tile (swizzled) and h (swizzled)
    {
        float4* W2s = (float4*)s2;                  // 8192 float4
        const float4* w2g = (const float4*)(W2 + (size_t)(ct * 64) * CH);
        #pragma unroll
        for (int t = 0; t < 32; t++) {
            const int i = tid + t * 256;
            const int c = i >> 7, q = i & 127;
            W2s[c * 128 + SWZ(q)] = w2g[i];
        }
        float4* hsv = (float4*)(s2 + 32768);        // 1536 float4
        const float4* hg = (const float4*)(g_h + (size_t)b * M * CH);
        #pragma unroll
        for (int t = 0; t < 6; t++) {
            const int i = tid + t * 256;
            const int m = i >> 7, q = i & 127;
            hsv[m * 128 + SWZ(q)] = hg[i];
        }
    }
    __syncthreads();

    const int c2 = tid >> 3;          // 0..31 -> rows 2c2, 2c2+1
    const int kc = tid & 7;           // k-chunk of 64 floats (16 float4)
    const int cA = 2 * c2, cB = 2 * c2 + 1;

    ull acc0[12], acc1[12];
    #pragma unroll
    for (int m = 0; m < 12; m++) { acc0[m] = 0ull; acc1[m] = 0ull; }

    const ulonglong2* W2u = (const ulonglong2*)s2;
    const ulonglong2* hu  = (const ulonglong2*)(s2 + 32768);
    const int kc16 = kc * 16;

    #pragma unroll 4
    for (int j = 0; j < 16; j++) {
        const int qs = kc16 + ((j ^ kc) & 15);
        const ulonglong2 wa = W2u[cA * 128 + qs];
        const ulonglong2 wb = W2u[cB * 128 + qs];
        #pragma unroll
        for (int m = 0; m < 12; m++) {
            const ulonglong2 hv = hu[m * 128 + qs];   // 8-distinct multicast
            acc0[m] = ffma2(wa.x, hv.x, acc0[m]);
            acc0[m] = ffma2(wa.y, hv.y, acc0[m]);
            acc1[m] = ffma2(wb.x, hv.x, acc1[m]);
            acc1[m] = ffma2(wb.y, hv.y, acc1[m]);
        }
    }
    __syncthreads();   // done with staged tiles; reuse s2

    float* part  = s2;                // [kc][c*12+m], stride 771
    float* ev_sm = s2 + 8 * 771;      // [c][m], stride 13 (832 floats)

    #pragma unroll
    for (int m = 0; m < 12; m++) {
        part[kc * 771 + cA * 12 + m] = unpk_add(acc0[m]);
        part[kc * 771 + cB * 12 + m] = unpk_add(acc1[m]);
    }
    __syncthreads();

    // combine 768 outputs (3/thread): e2 -> sigmoid -> mask -> exp
    #pragma unroll
    for (int t = 0; t < 3; t++) {
        const int idx = tid + t * 256;        // = c*12 + m
        const int c = idx / 12, m = idx - 12 * c;
        float e2v = 0.f;
        #pragma unroll
        for (int kk = 0; kk < 8; kk++) e2v += part[kk * 771 + idx];
        const int bm = b * M + m;
        const float cv = g_cov[(size_t)bm * C + ct * 64 + c];
        const float sg = 1.f / (1.f + __expf(-e2v));
        ev_sm[c * 13 + m] = (cv > 0.f) ? __expf(sg) : 0.f;
    }
    __syncthreads();

    // softmax rows: 24 (n,m) pairs over 8 warps; lanes = k
    #pragma unroll
    for (int it = 0; it < 3; it++) {
        const int p = it * 8 + w;             // 0..23
        const int n = p / 12, m = p - 12 * n;
        const float v = ev_sm[(n * 32 + lane) * 13 + m];
        float s = v;
        #pragma unroll
        for (int off = 16; off; off >>= 1) s += __shfl_xor_sync(0xffffffffu, s, off);
        g_att[(size_t)(b * M + m) * C + (ct * 2 + n) * NN + lane] = v / s;
    }
}

// ---------------------------------------------------------------------------
// k3: per bm, 256 thr. Pure AV: out[n][d=tid] = sum_k att[n][k] * x[k][d].
// Also resets g_scnt for the next graph replay.
// ---------------------------------------------------------------------------
__global__ void __launch_bounds__(256) k3_av(const float* __restrict__ x,
                                             float* __restrict__ out) {
    const int bm = blockIdx.x;
    __shared__ float xs[NN * D];   // 32 KB
    __shared__ float att[C];       // 4 KB

    if (blockIdx.x == 0 && threadIdx.x == 0) atomicExch(&g_scnt, 0);

    const int tid = threadIdx.x;
    const float4* xg4 = (const float4*)(x + (size_t)bm * (NN * D));
    float4* xs4 = (float4*)xs;
    #pragma unroll
    for (int i = 0; i < 8; i++) xs4[tid + i * 256] = xg4[tid + i * 256];

    ((float4*)att)[tid] = ((const float4*)(g_att + (size_t)bm * C))[tid];
    __syncthreads();

    ull xv2[16];
    #pragma unroll
    for (int kk = 0; kk < 16; kk++)
        xv2[kk] = pk2(xs[(2 * kk) * D + tid], xs[(2 * kk + 1) * D + tid]);

    float* ot = out + (size_t)bm * (NN * D);
    #pragma unroll 4
    for (int n = 0; n < NN; n++) {
        const ulonglong2* ar = (const ulonglong2*)(att + n * NN);
        ull a2 = 0ull;
        #pragma unroll
        for (int jj = 0; jj < 8; jj++) {
            const ulonglong2 bv = ar[jj];        // broadcast LDS.128
            a2 = ffma2(bv.x, xv2[2 * jj], a2);
            a2 = ffma2(bv.y, xv2[2 * jj + 1], a2);
        }
        ot[n * D + tid] = unpk_add(a2);
    }
}

// ---------------------------------------------------------------------------
extern "C" void kernel_launch(void* const* d_in, const int* in_sizes, int n_in,
                              void* d_out, int out_size) {
    const float* x  = (const float*)d_in[0];
    const float* W1 = (const float*)d_in[1];
    const float* W2 = (const float*)d_in[2];
    float* out = (float*)d_out;

    const int smemA = (8192 + 8448 + 256 + 32) * sizeof(float);  // 67712 B
    const int smemB = (32768 + 6144) * sizeof(float);            // 155648 B
    cudaFuncSetAttribute(kA, cudaFuncAttributeMaxDynamicSharedMemorySize, smemA);
    cudaFuncSetAttribute(k2_gemm_softmax, cudaFuncAttributeMaxDynamicSharedMemorySize, smemB);

    kA<<<BM + 16, 256, smemA>>>(x, W1);
    k2_gemm_softmax<<<dim3(16, B), 256, smemB>>>(W2);
    k3_av<<<BM, 256>>>(x, out);
}